// round 1
// baseline (speedup 1.0000x reference)
#include <cuda_runtime.h>
#include <math.h>

// Problem constants
#define BN 4
#define KN 16
#define HW (512*512)
#define LOG_2PI 1.8378770664093453f

// Reduction config
#define KG 4            // k-groups
#define KPT 4           // k per thread (KG*KPT == KN)
#define CHUNKS 32       // pixel chunks per (b, kgroup)
#define RTHREADS 256
#define NSTAT 10        // SP, Sx0..2, Sxx00,01,02,11,12,22

// Deterministic scratch (no allocations allowed)
__device__ float g_part[BN * KG * CHUNKS * KPT * NSTAT];
__device__ float g_params[BN * KN * NSTAT];

// ---------------------------------------------------------------------------
// Pass A: per-(b,k) partial sufficient statistics. No atomics -> deterministic.
// grid = (CHUNKS, KG, BN), block = RTHREADS
// ---------------------------------------------------------------------------
__global__ __launch_bounds__(RTHREADS)
void gmm_reduce_kernel(const float* __restrict__ P, const float* __restrict__ I) {
    const int b = blockIdx.z, kg = blockIdx.y, chunk = blockIdx.x;
    const int tid = threadIdx.x;

    const float* __restrict__ I0 = I + (size_t)(b * 3 + 0) * HW;
    const float* __restrict__ I1 = I + (size_t)(b * 3 + 1) * HW;
    const float* __restrict__ I2 = I + (size_t)(b * 3 + 2) * HW;
    const float* __restrict__ Pb = P + ((size_t)b * KN + (size_t)kg * KPT) * HW;

    float acc[KPT][NSTAT];
#pragma unroll
    for (int j = 0; j < KPT; j++)
#pragma unroll
        for (int s = 0; s < NSTAT; s++) acc[j][s] = 0.0f;

    const int stride = CHUNKS * RTHREADS;
    for (int p = chunk * RTHREADS + tid; p < HW; p += stride) {
        const float x0 = I0[p], x1 = I1[p], x2 = I2[p];
        const float x00 = x0 * x0, x01 = x0 * x1, x02 = x0 * x2;
        const float x11 = x1 * x1, x12 = x1 * x2, x22 = x2 * x2;
#pragma unroll
        for (int j = 0; j < KPT; j++) {
            const float w = Pb[(size_t)j * HW + p];
            acc[j][0] += w;
            acc[j][1] += w * x0;
            acc[j][2] += w * x1;
            acc[j][3] += w * x2;
            acc[j][4] += w * x00;
            acc[j][5] += w * x01;
            acc[j][6] += w * x02;
            acc[j][7] += w * x11;
            acc[j][8] += w * x12;
            acc[j][9] += w * x22;
        }
    }

    // warp reduce all 40 accumulators
#pragma unroll
    for (int j = 0; j < KPT; j++)
#pragma unroll
        for (int s = 0; s < NSTAT; s++)
#pragma unroll
            for (int off = 16; off > 0; off >>= 1)
                acc[j][s] += __shfl_down_sync(0xffffffffu, acc[j][s], off);

    __shared__ float sh[RTHREADS / 32][KPT * NSTAT];
    const int warp = tid >> 5, lane = tid & 31;
    if (lane == 0) {
#pragma unroll
        for (int j = 0; j < KPT; j++)
#pragma unroll
            for (int s = 0; s < NSTAT; s++)
                sh[warp][j * NSTAT + s] = acc[j][s];
    }
    __syncthreads();

    if (tid < KPT * NSTAT) {
        float v = 0.0f;
#pragma unroll
        for (int w = 0; w < RTHREADS / 32; w++) v += sh[w][tid];
        g_part[((size_t)(b * KG + kg) * CHUNKS + chunk) * (KPT * NSTAT) + tid] = v;
    }
}

// ---------------------------------------------------------------------------
// Pass B: finalize per-(b,k) params. 1 block, 64 threads, deterministic order.
// params layout per (b,k): mu0,mu1,mu2, 0.5*i00, 0.5*i11, 0.5*i22, i01,i02,i12, logcoef
// ---------------------------------------------------------------------------
__global__ void gmm_params_kernel() {
    const int t = threadIdx.x;
    if (t >= BN * KN) return;
    const int b = t / KN, k = t % KN;
    const int kg = k / KPT, j = k % KPT;

    float s[NSTAT];
#pragma unroll
    for (int i = 0; i < NSTAT; i++) s[i] = 0.0f;
    for (int c = 0; c < CHUNKS; c++) {
        const float* p = &g_part[((size_t)(b * KG + kg) * CHUNKS + c) * (KPT * NSTAT) + j * NSTAT];
#pragma unroll
        for (int i = 0; i < NSTAT; i++) s[i] += p[i];
    }

    const float SP = s[0];
    const float denom = 1e-5f + SP;
    const float rd = 1.0f / denom;
    const float mu0 = s[1] * rd, mu1 = s[2] * rd, mu2 = s[3] * rd;

    const float c00 = (s[4] - 2.0f * mu0 * s[1] + SP * mu0 * mu0) * rd + 1e-3f;
    const float c01 = (s[5] - mu0 * s[2] - mu1 * s[1] + SP * mu0 * mu1) * rd;
    const float c02 = (s[6] - mu0 * s[3] - mu2 * s[1] + SP * mu0 * mu2) * rd;
    const float c11 = (s[7] - 2.0f * mu1 * s[2] + SP * mu1 * mu1) * rd + 1e-3f;
    const float c12 = (s[8] - mu1 * s[3] - mu2 * s[2] + SP * mu1 * mu2) * rd;
    const float c22 = (s[9] - 2.0f * mu2 * s[3] + SP * mu2 * mu2) * rd + 1e-3f;

    const float m00 = c11 * c22 - c12 * c12;
    const float m01 = c02 * c12 - c01 * c22;
    const float m02 = c01 * c12 - c02 * c11;
    const float det = c00 * m00 + c01 * m01 + c02 * m02;
    const float inv = 1.0f / det;

    const float i00 = m00 * inv;
    const float i01 = m01 * inv;
    const float i02 = m02 * inv;
    const float i11 = (c00 * c22 - c02 * c02) * inv;
    const float i12 = (c01 * c02 - c00 * c12) * inv;
    const float i22 = (c00 * c11 - c01 * c01) * inv;

    const float alpha = SP * (1.0f / (float)HW);
    const float logcoef = logf(alpha) - 0.5f * (3.0f * LOG_2PI + logf(det));

    float* out = &g_params[(size_t)(b * KN + k) * NSTAT];
    out[0] = mu0; out[1] = mu1; out[2] = mu2;
    out[3] = 0.5f * i00; out[4] = 0.5f * i11; out[5] = 0.5f * i22;
    out[6] = i01; out[7] = i02; out[8] = i12;
    out[9] = logcoef;
}

// ---------------------------------------------------------------------------
// Pass C: E-step. Each thread = 1 pixel, all 16 classes.
// grid = (HW/256, BN), block = 256
// ---------------------------------------------------------------------------
__global__ __launch_bounds__(256)
void gmm_estep_kernel(const float* __restrict__ I, float* __restrict__ out) {
    const int b = blockIdx.y;
    const int p = blockIdx.x * blockDim.x + threadIdx.x;

    __shared__ float sp[KN * NSTAT];
    if (threadIdx.x < KN * NSTAT)
        sp[threadIdx.x] = g_params[(size_t)b * KN * NSTAT + threadIdx.x];
    __syncthreads();

    const float x0 = I[(size_t)(b * 3 + 0) * HW + p];
    const float x1 = I[(size_t)(b * 3 + 1) * HW + p];
    const float x2 = I[(size_t)(b * 3 + 2) * HW + p];

    float q[KN];
    float sum = 0.0f;
#pragma unroll
    for (int k = 0; k < KN; k++) {
        const float* pr = &sp[k * NSTAT];
        const float d0 = x0 - pr[0];
        const float d1 = x1 - pr[1];
        const float d2 = x2 - pr[2];
        const float quad = pr[3] * d0 * d0 + pr[4] * d1 * d1 + pr[5] * d2 * d2
                         + pr[6] * (d0 * d1) + pr[7] * (d0 * d2) + pr[8] * (d1 * d2);
        const float v = __expf(pr[9] - quad);
        q[k] = v;
        sum += v;
    }
    const float r = 1.0f / (1e-5f + sum);
    const size_t base = (size_t)b * KN * HW + p;
#pragma unroll
    for (int k = 0; k < KN; k++)
        out[base + (size_t)k * HW] = q[k] * r;
}

extern "C" void kernel_launch(void* const* d_in, const int* in_sizes, int n_in,
                              void* d_out, int out_size) {
    const float* Pij = (const float*)d_in[0];
    const float* I   = (const float*)d_in[1];
    float* out = (float*)d_out;

    dim3 gA(CHUNKS, KG, BN);
    gmm_reduce_kernel<<<gA, RTHREADS>>>(Pij, I);
    gmm_params_kernel<<<1, 64>>>();
    dim3 gC(HW / 256, BN);
    gmm_estep_kernel<<<gC, 256>>>(I, out);
}

// round 2
// speedup vs baseline: 1.4407x; 1.4407x over previous
#include <cuda_runtime.h>
#include <math.h>

// Problem constants
#define BN 4
#define KN 16
#define HW (512*512)
#define HW4 (HW/4)
#define LOG_2PI 1.8378770664093453f

// Reduction config
#define KG 8            // k-groups
#define KPT 2           // k per thread (KG*KPT == KN)
#define CHUNKS 32       // pixel chunks per (b, kgroup)
#define RTHREADS 256
#define NSTAT 10        // SP, Sx0..2, Sxx00,01,02,11,12,22

// Deterministic scratch (no allocations allowed)
__device__ float g_part[BN * KG * CHUNKS * KPT * NSTAT];
__device__ float g_params[BN * KN * NSTAT];

// ---------------------------------------------------------------------------
// Pass A: per-(b,k) partial sufficient statistics, float4 loads.
// grid = (CHUNKS, KG, BN), block = RTHREADS. No atomics -> deterministic.
// ---------------------------------------------------------------------------
__global__ __launch_bounds__(RTHREADS)
void gmm_reduce_kernel(const float* __restrict__ P, const float* __restrict__ I) {
    const int b = blockIdx.z, kg = blockIdx.y, chunk = blockIdx.x;
    const int tid = threadIdx.x;

    const float4* __restrict__ I0 = (const float4*)(I + (size_t)(b * 3 + 0) * HW);
    const float4* __restrict__ I1 = (const float4*)(I + (size_t)(b * 3 + 1) * HW);
    const float4* __restrict__ I2 = (const float4*)(I + (size_t)(b * 3 + 2) * HW);
    const float4* __restrict__ Pb = (const float4*)(P + ((size_t)b * KN + (size_t)kg * KPT) * HW);

    float acc[KPT][NSTAT];
#pragma unroll
    for (int j = 0; j < KPT; j++)
#pragma unroll
        for (int s = 0; s < NSTAT; s++) acc[j][s] = 0.0f;

    const int stride = CHUNKS * RTHREADS;
#pragma unroll 2
    for (int p = chunk * RTHREADS + tid; p < HW4; p += stride) {
        const float4 a0 = I0[p];
        const float4 a1 = I1[p];
        const float4 a2 = I2[p];
        float4 w[KPT];
#pragma unroll
        for (int j = 0; j < KPT; j++)
            w[j] = __ldcs(&Pb[(size_t)j * HW4 + p]);

        const float x0[4] = {a0.x, a0.y, a0.z, a0.w};
        const float x1[4] = {a1.x, a1.y, a1.z, a1.w};
        const float x2[4] = {a2.x, a2.y, a2.z, a2.w};
#pragma unroll
        for (int l = 0; l < 4; l++) {
            const float v0 = x0[l], v1 = x1[l], v2 = x2[l];
            const float p00 = v0 * v0, p01 = v0 * v1, p02 = v0 * v2;
            const float p11 = v1 * v1, p12 = v1 * v2, p22 = v2 * v2;
#pragma unroll
            for (int j = 0; j < KPT; j++) {
                const float wl = (l == 0) ? w[j].x : (l == 1) ? w[j].y : (l == 2) ? w[j].z : w[j].w;
                acc[j][0] += wl;
                acc[j][1] = fmaf(wl, v0, acc[j][1]);
                acc[j][2] = fmaf(wl, v1, acc[j][2]);
                acc[j][3] = fmaf(wl, v2, acc[j][3]);
                acc[j][4] = fmaf(wl, p00, acc[j][4]);
                acc[j][5] = fmaf(wl, p01, acc[j][5]);
                acc[j][6] = fmaf(wl, p02, acc[j][6]);
                acc[j][7] = fmaf(wl, p11, acc[j][7]);
                acc[j][8] = fmaf(wl, p12, acc[j][8]);
                acc[j][9] = fmaf(wl, p22, acc[j][9]);
            }
        }
    }

    // warp reduce all KPT*NSTAT accumulators
#pragma unroll
    for (int j = 0; j < KPT; j++)
#pragma unroll
        for (int s = 0; s < NSTAT; s++)
#pragma unroll
            for (int off = 16; off > 0; off >>= 1)
                acc[j][s] += __shfl_down_sync(0xffffffffu, acc[j][s], off);

    __shared__ float sh[RTHREADS / 32][KPT * NSTAT];
    const int warp = tid >> 5, lane = tid & 31;
    if (lane == 0) {
#pragma unroll
        for (int j = 0; j < KPT; j++)
#pragma unroll
            for (int s = 0; s < NSTAT; s++)
                sh[warp][j * NSTAT + s] = acc[j][s];
    }
    __syncthreads();

    if (tid < KPT * NSTAT) {
        float v = 0.0f;
#pragma unroll
        for (int w = 0; w < RTHREADS / 32; w++) v += sh[w][tid];
        g_part[((size_t)(b * KG + kg) * CHUNKS + chunk) * (KPT * NSTAT) + tid] = v;
    }
}

// ---------------------------------------------------------------------------
// Pass B: finalize per-(b,k) params. 1 block, 64 threads, deterministic order.
// params layout per (b,k): mu0,mu1,mu2, 0.5*i00, 0.5*i11, 0.5*i22, i01,i02,i12, logcoef
// ---------------------------------------------------------------------------
__global__ void gmm_params_kernel() {
    const int t = threadIdx.x;
    if (t >= BN * KN) return;
    const int b = t / KN, k = t % KN;
    const int kg = k / KPT, j = k % KPT;

    float s[NSTAT];
#pragma unroll
    for (int i = 0; i < NSTAT; i++) s[i] = 0.0f;
    for (int c = 0; c < CHUNKS; c++) {
        const float* p = &g_part[((size_t)(b * KG + kg) * CHUNKS + c) * (KPT * NSTAT) + j * NSTAT];
#pragma unroll
        for (int i = 0; i < NSTAT; i++) s[i] += p[i];
    }

    const float SP = s[0];
    const float denom = 1e-5f + SP;
    const float rd = 1.0f / denom;
    const float mu0 = s[1] * rd, mu1 = s[2] * rd, mu2 = s[3] * rd;

    const float c00 = (s[4] - 2.0f * mu0 * s[1] + SP * mu0 * mu0) * rd + 1e-3f;
    const float c01 = (s[5] - mu0 * s[2] - mu1 * s[1] + SP * mu0 * mu1) * rd;
    const float c02 = (s[6] - mu0 * s[3] - mu2 * s[1] + SP * mu0 * mu2) * rd;
    const float c11 = (s[7] - 2.0f * mu1 * s[2] + SP * mu1 * mu1) * rd + 1e-3f;
    const float c12 = (s[8] - mu1 * s[3] - mu2 * s[2] + SP * mu1 * mu2) * rd;
    const float c22 = (s[9] - 2.0f * mu2 * s[3] + SP * mu2 * mu2) * rd + 1e-3f;

    const float m00 = c11 * c22 - c12 * c12;
    const float m01 = c02 * c12 - c01 * c22;
    const float m02 = c01 * c12 - c02 * c11;
    const float det = c00 * m00 + c01 * m01 + c02 * m02;
    const float inv = 1.0f / det;

    const float i00 = m00 * inv;
    const float i01 = m01 * inv;
    const float i02 = m02 * inv;
    const float i11 = (c00 * c22 - c02 * c02) * inv;
    const float i12 = (c01 * c02 - c00 * c12) * inv;
    const float i22 = (c00 * c11 - c01 * c01) * inv;

    const float alpha = SP * (1.0f / (float)HW);
    const float logcoef = logf(alpha) - 0.5f * (3.0f * LOG_2PI + logf(det));

    float* out = &g_params[(size_t)(b * KN + k) * NSTAT];
    out[0] = mu0; out[1] = mu1; out[2] = mu2;
    out[3] = 0.5f * i00; out[4] = 0.5f * i11; out[5] = 0.5f * i22;
    out[6] = i01; out[7] = i02; out[8] = i12;
    out[9] = logcoef;
}

// ---------------------------------------------------------------------------
// Pass C: E-step, 4 pixels per thread (float4).
// grid = (HW4/256, BN), block = 256
// ---------------------------------------------------------------------------
__global__ __launch_bounds__(256)
void gmm_estep_kernel(const float* __restrict__ I, float* __restrict__ out) {
    const int b = blockIdx.y;
    const int p = blockIdx.x * blockDim.x + threadIdx.x;

    __shared__ float sp[KN * NSTAT];
    if (threadIdx.x < KN * NSTAT)
        sp[threadIdx.x] = g_params[(size_t)b * KN * NSTAT + threadIdx.x];
    __syncthreads();

    const float4 a0 = ((const float4*)(I + (size_t)(b * 3 + 0) * HW))[p];
    const float4 a1 = ((const float4*)(I + (size_t)(b * 3 + 1) * HW))[p];
    const float4 a2 = ((const float4*)(I + (size_t)(b * 3 + 2) * HW))[p];

    float4 q[KN];
    float4 sum = make_float4(0.f, 0.f, 0.f, 0.f);
#pragma unroll
    for (int k = 0; k < KN; k++) {
        const float* pr = &sp[k * NSTAT];
        const float m0 = pr[0], m1 = pr[1], m2 = pr[2];
        const float h00 = pr[3], h11 = pr[4], h22 = pr[5];
        const float h01 = pr[6], h02 = pr[7], h12 = pr[8];
        const float lc = pr[9];

        // lane x
        {
            const float d0 = a0.x - m0, d1 = a1.x - m1, d2 = a2.x - m2;
            const float quad = h00*d0*d0 + h11*d1*d1 + h22*d2*d2 + h01*(d0*d1) + h02*(d0*d2) + h12*(d1*d2);
            q[k].x = __expf(lc - quad); sum.x += q[k].x;
        }
        { // lane y
            const float d0 = a0.y - m0, d1 = a1.y - m1, d2 = a2.y - m2;
            const float quad = h00*d0*d0 + h11*d1*d1 + h22*d2*d2 + h01*(d0*d1) + h02*(d0*d2) + h12*(d1*d2);
            q[k].y = __expf(lc - quad); sum.y += q[k].y;
        }
        { // lane z
            const float d0 = a0.z - m0, d1 = a1.z - m1, d2 = a2.z - m2;
            const float quad = h00*d0*d0 + h11*d1*d1 + h22*d2*d2 + h01*(d0*d1) + h02*(d0*d2) + h12*(d1*d2);
            q[k].z = __expf(lc - quad); sum.z += q[k].z;
        }
        { // lane w
            const float d0 = a0.w - m0, d1 = a1.w - m1, d2 = a2.w - m2;
            const float quad = h00*d0*d0 + h11*d1*d1 + h22*d2*d2 + h01*(d0*d1) + h02*(d0*d2) + h12*(d1*d2);
            q[k].w = __expf(lc - quad); sum.w += q[k].w;
        }
    }
    const float rx = 1.0f / (1e-5f + sum.x);
    const float ry = 1.0f / (1e-5f + sum.y);
    const float rz = 1.0f / (1e-5f + sum.z);
    const float rw = 1.0f / (1e-5f + sum.w);

    float4* __restrict__ o4 = (float4*)(out + (size_t)b * KN * HW);
#pragma unroll
    for (int k = 0; k < KN; k++) {
        float4 v;
        v.x = q[k].x * rx; v.y = q[k].y * ry; v.z = q[k].z * rz; v.w = q[k].w * rw;
        o4[(size_t)k * HW4 + p] = v;
    }
}

extern "C" void kernel_launch(void* const* d_in, const int* in_sizes, int n_in,
                              void* d_out, int out_size) {
    const float* Pij = (const float*)d_in[0];
    const float* I   = (const float*)d_in[1];
    float* out = (float*)d_out;

    dim3 gA(CHUNKS, KG, BN);
    gmm_reduce_kernel<<<gA, RTHREADS>>>(Pij, I);
    gmm_params_kernel<<<1, 64>>>();
    dim3 gC(HW4 / 256, BN);
    gmm_estep_kernel<<<gC, 256>>>(I, out);
}